// round 1
// baseline (speedup 1.0000x reference)
#include <cuda_runtime.h>

typedef unsigned long long ull;

#define BB 16
#define CC 64
#define NN 4096      // H*W
#define NP 1024      // pooled positions (32*32)

// ---------------- scratch (device globals; no allocation) ----------------
__device__ float g_theta[BB * NN * 8];   // [b][n][8]
__device__ float g_phi[BB * NP * 8];     // [b][p][8]
__device__ float g_gv[BB * NP * 32];     // [b][p][32]

// ---------------- f32x2 helpers ----------------
__device__ __forceinline__ ull pack2(float lo, float hi) {
    ull r; asm("mov.b64 %0, {%1,%2};" : "=l"(r) : "f"(lo), "f"(hi)); return r;
}
__device__ __forceinline__ void unpack2(ull v, float& lo, float& hi) {
    asm("mov.b64 {%0,%1}, %2;" : "=f"(lo), "=f"(hi) : "l"(v));
}
__device__ __forceinline__ void fma2(ull& d, ull a, ull b) {
    asm("fma.rn.f32x2 %0, %1, %2, %0;" : "+l"(d) : "l"(a), "l"(b));
}
__device__ __forceinline__ ull mul2(ull a, ull b) {
    ull d; asm("mul.rn.f32x2 %0, %1, %2;" : "=l"(d) : "l"(a), "l"(b)); return d;
}

// =========================================================================
// Kernel 1: 1x1 conv projections + 2x2 maxpool.
// One thread per pooled position (16384 total). Computes theta/phi/g for the
// 4 underlying pixels; theta written full-res, phi/g max-pooled.
// Weight smem layout: ws[k][48] : [0:8)=theta_w[:,k], [8:16)=phi_w, [16:48)=g_w
// =========================================================================
__global__ void __launch_bounds__(128, 1)
proj_kernel(const float* __restrict__ x,
            const float* __restrict__ tw,
            const float* __restrict__ pw,
            const float* __restrict__ gw)
{
    __shared__ float ws[64 * 48];
    for (int i = threadIdx.x; i < 64 * 48; i += 128) {
        int k = i / 48, o = i % 48;
        float v;
        if (o < 8)        v = tw[o * 64 + k];
        else if (o < 16)  v = pw[(o - 8) * 64 + k];
        else              v = gw[(o - 16) * 64 + k];
        ws[i] = v;
    }
    __syncthreads();

    int p  = blockIdx.x * 128 + threadIdx.x;  // global pooled index
    int b  = p >> 10;
    int pp = p & 1023;
    int hp = pp >> 5, wp = pp & 31;

    const float* xb = x + (size_t)b * CC * NN;

    float best[40];
#pragma unroll
    for (int c = 0; c < 40; c++) best[c] = -1e30f;

    for (int dy = 0; dy < 2; dy++) {
        ull acc0[24], acc1[24];
#pragma unroll
        for (int c = 0; c < 24; c++) { acc0[c] = 0ull; acc1[c] = 0ull; }

        const float* xrow = xb + (2 * hp + dy) * 64 + 2 * wp;
#pragma unroll 4
        for (int k = 0; k < 64; k++) {
            float2 xv = *(const float2*)(xrow + (size_t)k * NN);
            ull a0 = pack2(xv.x, xv.x);
            ull a1 = pack2(xv.y, xv.y);
            const ull* w2 = (const ull*)(ws + k * 48);
#pragma unroll
            for (int c = 0; c < 24; c++) {
                ull w = w2[c];
                fma2(acc0[c], a0, w);
                fma2(acc1[c], a1, w);
            }
        }

        // theta write (full-res), outputs 0..7 = pairs 0..3
        int n0 = (2 * hp + dy) * 64 + 2 * wp;
        {
            float t[8];
            unpack2(acc0[0], t[0], t[1]); unpack2(acc0[1], t[2], t[3]);
            unpack2(acc0[2], t[4], t[5]); unpack2(acc0[3], t[6], t[7]);
            float4* dst = (float4*)(g_theta + ((size_t)b * NN + n0) * 8);
            dst[0] = make_float4(t[0], t[1], t[2], t[3]);
            dst[1] = make_float4(t[4], t[5], t[6], t[7]);
            unpack2(acc1[0], t[0], t[1]); unpack2(acc1[1], t[2], t[3]);
            unpack2(acc1[2], t[4], t[5]); unpack2(acc1[3], t[6], t[7]);
            float4* dst1 = (float4*)(g_theta + ((size_t)b * NN + n0 + 1) * 8);
            dst1[0] = make_float4(t[0], t[1], t[2], t[3]);
            dst1[1] = make_float4(t[4], t[5], t[6], t[7]);
        }
        // pool phi (outputs 8..15) + g (16..47) = pairs 4..23 -> best[0..39]
#pragma unroll
        for (int c = 4; c < 24; c++) {
            float u, v;
            unpack2(acc0[c], u, v);
            best[2 * c - 8]     = fmaxf(best[2 * c - 8], u);
            best[2 * c - 8 + 1] = fmaxf(best[2 * c - 8 + 1], v);
            unpack2(acc1[c], u, v);
            best[2 * c - 8]     = fmaxf(best[2 * c - 8], u);
            best[2 * c - 8 + 1] = fmaxf(best[2 * c - 8 + 1], v);
        }
    }

    {   // phi: best[0..7]
        float4* dst = (float4*)(g_phi + ((size_t)b * NP + pp) * 8);
        dst[0] = make_float4(best[0], best[1], best[2], best[3]);
        dst[1] = make_float4(best[4], best[5], best[6], best[7]);
    }
    {   // g: best[8..39]
        float4* dst = (float4*)(g_gv + ((size_t)b * NP + pp) * 32);
#pragma unroll
        for (int c = 0; c < 8; c++)
            dst[c] = make_float4(best[8 + 4 * c], best[9 + 4 * c],
                                 best[10 + 4 * c], best[11 + 4 * c]);
    }
}

// =========================================================================
// Kernel 2: fused attention + o-projection + residual.
// Grid (8 tiles, 16 batches), 128 threads, 4 queries/thread (512 q/CTA).
// phi[1024][8], g[1024][32], o_w[64][32] staged in 168 KB dynamic smem.
// All threads share key index m -> all LDS are warp broadcasts.
// =========================================================================
#define SMEM_PHI  0
#define SMEM_G    8192
#define SMEM_OW   (8192 + 32768)
#define SMEM_FLTS (8192 + 32768 + 2048)
#define SMEM_BYTES (SMEM_FLTS * 4)

__global__ void __launch_bounds__(128, 1)
attn_kernel(const float* __restrict__ x,
            const float* __restrict__ ow,
            const float* __restrict__ gamma_p,
            float* __restrict__ out)
{
    extern __shared__ float sm[];
    float* phi_s = sm + SMEM_PHI;
    float* g_s   = sm + SMEM_G;
    float* ow_s  = sm + SMEM_OW;

    const int tid  = threadIdx.x;
    const int b    = blockIdx.y;
    const int tile = blockIdx.x;

    // ---- stage smem (straight float4 copies; layouts match) ----
    {
        const float4* ps = (const float4*)(g_phi + (size_t)b * NP * 8);
        float4* pd = (float4*)phi_s;
        for (int i = tid; i < NP * 8 / 4; i += 128) pd[i] = ps[i];
        const float4* gs = (const float4*)(g_gv + (size_t)b * NP * 32);
        float4* gd = (float4*)g_s;
        for (int i = tid; i < NP * 32 / 4; i += 128) gd[i] = gs[i];
        const float4* os = (const float4*)ow;
        float4* od = (float4*)ow_s;
        for (int i = tid; i < 64 * 32 / 4; i += 128) od[i] = os[i];
    }
    __syncthreads();

    const int q0 = tile * 512 + tid;   // queries q0 + 128*i, i<4

    // theta for my 4 queries: channel pairs straight from global (8B aligned)
    ull th[4][4];
#pragma unroll
    for (int i = 0; i < 4; i++) {
        const ull* tp = (const ull*)(g_theta + ((size_t)b * NN + q0 + i * 128) * 8);
        th[i][0] = tp[0]; th[i][1] = tp[1]; th[i][2] = tp[2]; th[i][3] = tp[3];
    }

    ull acc[4][16];
#pragma unroll
    for (int i = 0; i < 4; i++)
#pragma unroll
        for (int c = 0; c < 16; c++) acc[i][c] = 0ull;
    float den[4] = {0.f, 0.f, 0.f, 0.f};

    const ull* phi2 = (const ull*)phi_s;   // [m][4 pairs]
    const ull* g2   = (const ull*)g_s;     // [m][16 pairs]

#pragma unroll 2
    for (int m = 0; m < NP; m++) {
        const ull* pm = phi2 + m * 4;
        ull p0 = pm[0], p1 = pm[1], p2 = pm[2], p3 = pm[3];

        ull ea[4];
#pragma unroll
        for (int i = 0; i < 4; i++) {
            ull s2 = mul2(th[i][0], p0);
            fma2(s2, th[i][1], p1);
            fma2(s2, th[i][2], p2);
            fma2(s2, th[i][3], p3);
            float slo, shi;
            unpack2(s2, slo, shi);
            float e = __expf(slo + shi);   // logits bounded; max-free softmax OK
            den[i] += e;
            ea[i] = pack2(e, e);
        }

        const ull* gm = g2 + m * 16;
#pragma unroll
        for (int cp = 0; cp < 16; cp++) {
            ull gval = gm[cp];
            fma2(acc[0][cp], ea[0], gval);
            fma2(acc[1][cp], ea[1], gval);
            fma2(acc[2][cp], ea[2], gval);
            fma2(acc[3][cp], ea[3], gval);
        }
    }

    // ---- epilogue: o = o_w @ attn ; out = gamma*o + x ----
    const float gamma = *gamma_p;
    const ull* ow2 = (const ull*)ow_s;     // [j][16 pairs]
#pragma unroll
    for (int i = 0; i < 4; i++) {
        const int q = q0 + i * 128;
        const float sc = gamma / den[i];   // fold 1/den and gamma together
        const float* xq = x + ((size_t)b * CC) * NN + q;
        float*       oq = out + ((size_t)b * CC) * NN + q;
        for (int j = 0; j < 64; j++) {
            const ull* wj = ow2 + j * 16;
            ull o2 = mul2(wj[0], acc[i][0]);
#pragma unroll
            for (int cp = 1; cp < 16; cp++) fma2(o2, wj[cp], acc[i][cp]);
            float oa, ob;
            unpack2(o2, oa, ob);
            oq[(size_t)j * NN] = fmaf(sc, oa + ob, xq[(size_t)j * NN]);
        }
    }
}

// =========================================================================
extern "C" void kernel_launch(void* const* d_in, const int* in_sizes, int n_in,
                              void* d_out, int out_size)
{
    const float* x     = (const float*)d_in[0];
    const float* tw    = (const float*)d_in[1];
    const float* pw    = (const float*)d_in[2];
    const float* gw    = (const float*)d_in[3];
    const float* ow    = (const float*)d_in[4];
    const float* gamma = (const float*)d_in[5];
    float* out = (float*)d_out;

    cudaFuncSetAttribute(attn_kernel,
                         cudaFuncAttributeMaxDynamicSharedMemorySize, SMEM_BYTES);

    proj_kernel<<<BB * NP / 128, 128>>>(x, tw, pw, gw);
    attn_kernel<<<dim3(8, BB), 128, SMEM_BYTES>>>(x, ow, gamma, out);
}

// round 2
// speedup vs baseline: 1.1416x; 1.1416x over previous
#include <cuda_runtime.h>

typedef unsigned long long ull;

#define BB 16
#define CC 64
#define NN 4096      // H*W
#define NP 1024      // pooled positions (32*32)

// ---------------- scratch (device globals; no allocation) ----------------
__device__ float g_theta[BB * NN * 8];   // [b][n][8]
__device__ float g_phi[BB * NP * 8];     // [b][p][8]
__device__ float g_gv[BB * NP * 32];     // [b][p][32]

// ---------------- f32x2 helpers ----------------
__device__ __forceinline__ ull pack2(float lo, float hi) {
    ull r; asm("mov.b64 %0, {%1,%2};" : "=l"(r) : "f"(lo), "f"(hi)); return r;
}
__device__ __forceinline__ void unpack2(ull v, float& lo, float& hi) {
    asm("mov.b64 {%0,%1}, %2;" : "=f"(lo), "=f"(hi) : "l"(v));
}
__device__ __forceinline__ void fma2(ull& d, ull a, ull b) {
    asm("fma.rn.f32x2 %0, %1, %2, %0;" : "+l"(d) : "l"(a), "l"(b));
}
__device__ __forceinline__ ull mul2(ull a, ull b) {
    ull d; asm("mul.rn.f32x2 %0, %1, %2;" : "=l"(d) : "l"(a), "l"(b)); return d;
}

// =========================================================================
// Kernel 1: 1x1 conv projections + 2x2 maxpool. (unchanged — not hot)
// =========================================================================
__global__ void __launch_bounds__(128, 1)
proj_kernel(const float* __restrict__ x,
            const float* __restrict__ tw,
            const float* __restrict__ pw,
            const float* __restrict__ gw)
{
    __shared__ float ws[64 * 48];
    for (int i = threadIdx.x; i < 64 * 48; i += 128) {
        int k = i / 48, o = i % 48;
        float v;
        if (o < 8)        v = tw[o * 64 + k];
        else if (o < 16)  v = pw[(o - 8) * 64 + k];
        else              v = gw[(o - 16) * 64 + k];
        ws[i] = v;
    }
    __syncthreads();

    int p  = blockIdx.x * 128 + threadIdx.x;
    int b  = p >> 10;
    int pp = p & 1023;
    int hp = pp >> 5, wp = pp & 31;

    const float* xb = x + (size_t)b * CC * NN;

    float best[40];
#pragma unroll
    for (int c = 0; c < 40; c++) best[c] = -1e30f;

    for (int dy = 0; dy < 2; dy++) {
        ull acc0[24], acc1[24];
#pragma unroll
        for (int c = 0; c < 24; c++) { acc0[c] = 0ull; acc1[c] = 0ull; }

        const float* xrow = xb + (2 * hp + dy) * 64 + 2 * wp;
#pragma unroll 4
        for (int k = 0; k < 64; k++) {
            float2 xv = *(const float2*)(xrow + (size_t)k * NN);
            ull a0 = pack2(xv.x, xv.x);
            ull a1 = pack2(xv.y, xv.y);
            const ull* w2 = (const ull*)(ws + k * 48);
#pragma unroll
            for (int c = 0; c < 24; c++) {
                ull w = w2[c];
                fma2(acc0[c], a0, w);
                fma2(acc1[c], a1, w);
            }
        }

        int n0 = (2 * hp + dy) * 64 + 2 * wp;
        {
            float t[8];
            unpack2(acc0[0], t[0], t[1]); unpack2(acc0[1], t[2], t[3]);
            unpack2(acc0[2], t[4], t[5]); unpack2(acc0[3], t[6], t[7]);
            float4* dst = (float4*)(g_theta + ((size_t)b * NN + n0) * 8);
            dst[0] = make_float4(t[0], t[1], t[2], t[3]);
            dst[1] = make_float4(t[4], t[5], t[6], t[7]);
            unpack2(acc1[0], t[0], t[1]); unpack2(acc1[1], t[2], t[3]);
            unpack2(acc1[2], t[4], t[5]); unpack2(acc1[3], t[6], t[7]);
            float4* dst1 = (float4*)(g_theta + ((size_t)b * NN + n0 + 1) * 8);
            dst1[0] = make_float4(t[0], t[1], t[2], t[3]);
            dst1[1] = make_float4(t[4], t[5], t[6], t[7]);
        }
#pragma unroll
        for (int c = 4; c < 24; c++) {
            float u, v;
            unpack2(acc0[c], u, v);
            best[2 * c - 8]     = fmaxf(best[2 * c - 8], u);
            best[2 * c - 8 + 1] = fmaxf(best[2 * c - 8 + 1], v);
            unpack2(acc1[c], u, v);
            best[2 * c - 8]     = fmaxf(best[2 * c - 8], u);
            best[2 * c - 8 + 1] = fmaxf(best[2 * c - 8 + 1], v);
        }
    }

    {
        float4* dst = (float4*)(g_phi + ((size_t)b * NP + pp) * 8);
        dst[0] = make_float4(best[0], best[1], best[2], best[3]);
        dst[1] = make_float4(best[4], best[5], best[6], best[7]);
    }
    {
        float4* dst = (float4*)(g_gv + ((size_t)b * NP + pp) * 32);
#pragma unroll
        for (int c = 0; c < 8; c++)
            dst[c] = make_float4(best[8 + 4 * c], best[9 + 4 * c],
                                 best[10 + 4 * c], best[11 + 4 * c]);
    }
}

// =========================================================================
// Kernel 2: fused attention + o-projection + residual.
// Grid (8 tiles, 16 batches), 256 threads, 2 queries/thread (512 q/CTA).
// 8 warps/SM = 2 per SMSP for latency hiding. m-loop unrolled x2.
// =========================================================================
#define THREADS 256
#define QPT 2
#define SMEM_PHI  0
#define SMEM_G    8192
#define SMEM_OW   (8192 + 32768)
#define SMEM_FLTS (8192 + 32768 + 2048)
#define SMEM_BYTES (SMEM_FLTS * 4)

__global__ void __launch_bounds__(THREADS, 1)
attn_kernel(const float* __restrict__ x,
            const float* __restrict__ ow,
            const float* __restrict__ gamma_p,
            float* __restrict__ out)
{
    extern __shared__ float sm[];
    float* phi_s = sm + SMEM_PHI;
    float* g_s   = sm + SMEM_G;
    float* ow_s  = sm + SMEM_OW;

    const int tid  = threadIdx.x;
    const int b    = blockIdx.y;
    const int tile = blockIdx.x;

    // ---- stage smem (straight float4 copies; layouts match) ----
    {
        const float4* ps = (const float4*)(g_phi + (size_t)b * NP * 8);
        float4* pd = (float4*)phi_s;
        for (int i = tid; i < NP * 8 / 4; i += THREADS) pd[i] = ps[i];
        const float4* gs = (const float4*)(g_gv + (size_t)b * NP * 32);
        float4* gd = (float4*)g_s;
        for (int i = tid; i < NP * 32 / 4; i += THREADS) gd[i] = gs[i];
        const float4* os = (const float4*)ow;
        float4* od = (float4*)ow_s;
        for (int i = tid; i < 64 * 32 / 4; i += THREADS) od[i] = os[i];
    }
    __syncthreads();

    const int q0 = tile * 512 + tid;   // queries q0 + 256*i, i<QPT

    ull th[QPT][4];
#pragma unroll
    for (int i = 0; i < QPT; i++) {
        const ull* tp = (const ull*)(g_theta + ((size_t)b * NN + q0 + i * THREADS) * 8);
        th[i][0] = tp[0]; th[i][1] = tp[1]; th[i][2] = tp[2]; th[i][3] = tp[3];
    }

    ull acc[QPT][16];
#pragma unroll
    for (int i = 0; i < QPT; i++)
#pragma unroll
        for (int c = 0; c < 16; c++) acc[i][c] = 0ull;
    float den[QPT];
#pragma unroll
    for (int i = 0; i < QPT; i++) den[i] = 0.f;

    const ull* phi2 = (const ull*)phi_s;   // [m][4 pairs]
    const ull* g2   = (const ull*)g_s;     // [m][16 pairs]

#pragma unroll 4
    for (int m = 0; m < NP; m++) {
        const ull* pm = phi2 + m * 4;
        ull p0 = pm[0], p1 = pm[1], p2 = pm[2], p3 = pm[3];

        ull ea[QPT];
#pragma unroll
        for (int i = 0; i < QPT; i++) {
            ull s2 = mul2(th[i][0], p0);
            fma2(s2, th[i][1], p1);
            fma2(s2, th[i][2], p2);
            fma2(s2, th[i][3], p3);
            float slo, shi;
            unpack2(s2, slo, shi);
            float e = __expf(slo + shi);   // logits bounded; max-free softmax OK
            den[i] += e;
            ea[i] = pack2(e, e);
        }

        const ull* gm = g2 + m * 16;
#pragma unroll
        for (int cp = 0; cp < 16; cp++) {
            ull gval = gm[cp];
#pragma unroll
            for (int i = 0; i < QPT; i++) fma2(acc[i][cp], ea[i], gval);
        }
    }

    // ---- epilogue: o = o_w @ attn ; out = gamma*o + x ----
    const float gamma = *gamma_p;
    const ull* ow2 = (const ull*)ow_s;     // [j][16 pairs]
#pragma unroll
    for (int i = 0; i < QPT; i++) {
        const int q = q0 + i * THREADS;
        const float sc = gamma / den[i];
        const float* xq = x + ((size_t)b * CC) * NN + q;
        float*       oq = out + ((size_t)b * CC) * NN + q;
        for (int j = 0; j < 64; j++) {
            const ull* wj = ow2 + j * 16;
            ull o2 = mul2(wj[0], acc[i][0]);
#pragma unroll
            for (int cp = 1; cp < 16; cp++) fma2(o2, wj[cp], acc[i][cp]);
            float oa, ob;
            unpack2(o2, oa, ob);
            oq[(size_t)j * NN] = fmaf(sc, oa + ob, xq[(size_t)j * NN]);
        }
    }
}

// =========================================================================
extern "C" void kernel_launch(void* const* d_in, const int* in_sizes, int n_in,
                              void* d_out, int out_size)
{
    const float* x     = (const float*)d_in[0];
    const float* tw    = (const float*)d_in[1];
    const float* pw    = (const float*)d_in[2];
    const float* gw    = (const float*)d_in[3];
    const float* ow    = (const float*)d_in[4];
    const float* gamma = (const float*)d_in[5];
    float* out = (float*)d_out;

    cudaFuncSetAttribute(attn_kernel,
                         cudaFuncAttributeMaxDynamicSharedMemorySize, SMEM_BYTES);

    proj_kernel<<<BB * NP / 128, 128>>>(x, tw, pw, gw);
    attn_kernel<<<dim3(8, BB), THREADS, SMEM_BYTES>>>(x, ow, gamma, out);
}